// round 12
// baseline (speedup 1.0000x reference)
#include <cuda_runtime.h>
#include <cuda_fp16.h>
#include <cstdint>

#define B_TOT 16384
#define F_DIM 50
#define E_DIM 64
#define D_DIM 128
#define NTHREADS 256
#define GRID_CTAS 296   // 148 SMs * 2 CTAs

// ---------------- helpers ----------------
__device__ __forceinline__ uint32_t smem_u32(const void* p) {
    uint32_t a;
    asm("{ .reg .u64 t; cvta.to.shared.u64 t, %1; cvt.u32.u64 %0, t; }" : "=r"(a) : "l"(p));
    return a;
}

__device__ __forceinline__ void cp_async16(uint32_t smem_addr, const void* gmem) {
    asm volatile("cp.async.cg.shared.global [%0], [%1], 16;" :: "r"(smem_addr), "l"(gmem));
}
__device__ __forceinline__ void cp_commit() { asm volatile("cp.async.commit_group;" ::: "memory"); }
__device__ __forceinline__ void cp_wait2() { asm volatile("cp.async.wait_group 2;" ::: "memory"); }

__device__ __forceinline__ void ldsm4t(uint32_t r[4], uint32_t addr) {
    asm volatile("ldmatrix.sync.aligned.m8n8.x4.trans.shared.b16 {%0,%1,%2,%3}, [%4];"
                 : "=r"(r[0]), "=r"(r[1]), "=r"(r[2]), "=r"(r[3]) : "r"(addr));
}

__device__ __forceinline__ void mma16816(float c[4], const uint32_t a[4], const uint32_t* b) {
    asm volatile(
        "mma.sync.aligned.m16n8k16.row.col.f32.f16.f16.f32 "
        "{%0,%1,%2,%3}, {%4,%5,%6,%7}, {%8,%9}, {%0,%1,%2,%3};"
        : "+f"(c[0]), "+f"(c[1]), "+f"(c[2]), "+f"(c[3])
        : "r"(a[0]), "r"(a[1]), "r"(a[2]), "r"(a[3]), "r"(b[0]), "r"(b[1]));
}

#define STS128(smem_addr, r0, r1, r2, r3) \
    asm volatile("st.shared.v4.b32 [%0], {%1, %2, %3, %4};" \
                 :: "r"(smem_addr), "r"(r0), "r"(r1), "r"(r2), "r"(r3) : "memory")

// Swizzled byte offset of element (k-row, n-col) in the 64x64 fp16 B tile.
// Rows are 128B; 16B atoms are XORed with (k&7) -> conflict-free STS + LDSM.
__device__ __forceinline__ uint32_t bt_off(int k, int n) {
    return (uint32_t)(k * 128 + ((((n >> 3) ^ k) & 7) << 4) + (n & 7) * 2);
}

// Pack theta[r][k0], theta[r][k0+1] as half2 (zero-padded beyond F_DIM).
__device__ __forceinline__ uint32_t ld_theta_h2(const float* theta, int r, int k0) {
    if (k0 < F_DIM) {   // k0 even, so k0 <= 48 implies k0+1 <= 49 valid
        float2 v = *reinterpret_cast<const float2*>(theta + r * F_DIM + k0);
        __half2 h = __floats2half2_rn(v.x, v.y);
        return *reinterpret_cast<uint32_t*>(&h);
    }
    return 0u;
}

// ---------------- kernel ----------------
__global__ void __launch_bounds__(NTHREADS, 2)
InnerProduct_65429531787441_kernel(const float* __restrict__ inputs,
                                   const float* __restrict__ theta,
                                   float* __restrict__ out) {
    __shared__ __align__(16) float stage[3][F_DIM * E_DIM];   // 3 x 12800 B ring
    __shared__ __align__(1024) __half bt[64 * 64];            // 8192 B swizzled B tile
    __shared__ float partial[2][D_DIM];                       // per-n-half row partials

    const int tid = threadIdx.x;
    const int lane = tid & 31;
    const int w = tid >> 5;          // 8 warps
    const int mg = w >> 1;           // m-group: rows [32*mg, 32*mg+32)
    const int ng = w & 1;            // n-group: cols [32*ng, 32*ng+32)
    const uint32_t bt_base = smem_u32(bt);
    uint32_t st_addr[3];
    st_addr[0] = smem_u32(&stage[0][0]);
    st_addr[1] = smem_u32(&stage[1][0]);
    st_addr[2] = smem_u32(&stage[2][0]);

    // Zero B rows 50..63 once (A frags are zero there, but avoid NaN garbage).
    if (tid < 112) reinterpret_cast<float4*>(bt)[400 + tid] = make_float4(0.f, 0.f, 0.f, 0.f);

    // ---- persistent A fragments: Theta rows [32*mg, 32*mg+32), fp16 ----
    uint32_t a[2][4][4];   // [m-tile][k-step][reg]
#pragma unroll
    for (int mt = 0; mt < 2; mt++)
#pragma unroll
        for (int ks = 0; ks < 4; ks++) {
            int r = mg * 32 + mt * 16 + (lane >> 2);
            int k0 = ks * 16 + (lane & 3) * 2;
            a[mt][ks][0] = ld_theta_h2(theta, r, k0);
            a[mt][ks][1] = ld_theta_h2(theta, r + 8, k0);
            a[mt][ks][2] = ld_theta_h2(theta, r, k0 + 8);
            a[mt][ks][3] = ld_theta_h2(theta, r + 8, k0 + 8);
        }
    __syncthreads();

    // ---- prologue: stage first two batches ----
    {
        const char* g0 = reinterpret_cast<const char*>(inputs + (size_t)blockIdx.x * (F_DIM * E_DIM));
        for (int i = tid; i < 800; i += NTHREADS) cp_async16(st_addr[0] + i * 16, g0 + i * 16);
        cp_commit();
        const int b1 = blockIdx.x + GRID_CTAS;
        if (b1 < B_TOT) {
            const char* g1 = reinterpret_cast<const char*>(inputs + (size_t)b1 * (F_DIM * E_DIM));
            for (int i = tid; i < 800; i += NTHREADS) cp_async16(st_addr[1] + i * 16, g1 + i * 16);
        }
        cp_commit();
    }

    int cur = 0;
    for (int b = blockIdx.x; b < B_TOT; b += GRID_CTAS) {
        // ---- prefetch b + 2*GRID into the stage consumed 2 iterations ago ----
        {
            const int bn = b + 2 * GRID_CTAS;
            if (bn < B_TOT) {
                const int pre = (cur + 2 >= 3) ? cur - 1 : cur + 2;
                const char* g = reinterpret_cast<const char*>(inputs + (size_t)bn * (F_DIM * E_DIM));
                for (int i = tid; i < 800; i += NTHREADS) cp_async16(st_addr[pre] + i * 16, g + i * 16);
            }
            cp_commit();            // constant one group per iteration (may be empty)
            cp_wait2();             // oldest group (batch b) complete
        }
        __syncthreads();

        // ---- convert f32 stage -> fp16 swizzled B tile (STS.128 granularity) ----
        {
            const float* sc = stage[cur];
#pragma unroll 2
            for (int i = tid; i < 400; i += NTHREADS) {   // 400 groups of 8 e-values
                int f = i >> 3;
                int e8 = (i & 7) * 8;
                const float4* p = reinterpret_cast<const float4*>(sc + f * 64 + e8);
                float4 v0 = p[0], v1 = p[1];
                __half2 h0 = __floats2half2_rn(v0.x, v0.y);
                __half2 h1 = __floats2half2_rn(v0.z, v0.w);
                __half2 h2 = __floats2half2_rn(v1.x, v1.y);
                __half2 h3 = __floats2half2_rn(v1.z, v1.w);
                uint32_t off = (uint32_t)(f * 128 + ((((e8 >> 3) ^ f) & 7) << 4));
                STS128(bt_base + off,
                       *reinterpret_cast<uint32_t*>(&h0), *reinterpret_cast<uint32_t*>(&h1),
                       *reinterpret_cast<uint32_t*>(&h2), *reinterpret_cast<uint32_t*>(&h3));
            }
        }
        __syncthreads();

        // ---- MMA: warp computes P(32m x 32n) = Theta_mg * X[:, 32ng:32ng+32) ----
        float c[2][4][4];
#pragma unroll
        for (int mt = 0; mt < 2; mt++)
#pragma unroll
            for (int nt = 0; nt < 4; nt++)
#pragma unroll
                for (int j = 0; j < 4; j++) c[mt][nt][j] = 0.f;

#pragma unroll
        for (int ks = 0; ks < 4; ks++) {
            uint32_t bf[4][2];
#pragma unroll
            for (int g = 0; g < 2; g++) {
                int t = lane >> 3;
                int k = ks * 16 + (t & 1) * 8 + (lane & 7);
                int n = ng * 32 + g * 16 + (t >> 1) * 8;
                uint32_t r4[4];
                ldsm4t(r4, bt_base + bt_off(k, n));
                bf[2 * g][0] = r4[0]; bf[2 * g][1] = r4[1];
                bf[2 * g + 1][0] = r4[2]; bf[2 * g + 1][1] = r4[3];
            }
#pragma unroll
            for (int nt = 0; nt < 4; nt++) {
                mma16816(c[0][nt], a[0][ks], bf[nt]);
                mma16816(c[1][nt], a[1][ks], bf[nt]);
            }
        }

        // ---- epilogue: per-warp partial sum over its 32 e-cols ----
#pragma unroll
        for (int mt = 0; mt < 2; mt++) {
            float s0 = 0.f, s1 = 0.f;
#pragma unroll
            for (int nt = 0; nt < 4; nt++) {
                s0 = fmaf(c[mt][nt][0], c[mt][nt][0], s0);
                s0 = fmaf(c[mt][nt][1], c[mt][nt][1], s0);
                s1 = fmaf(c[mt][nt][2], c[mt][nt][2], s1);
                s1 = fmaf(c[mt][nt][3], c[mt][nt][3], s1);
            }
            s0 += __shfl_xor_sync(0xFFFFFFFFu, s0, 1);
            s0 += __shfl_xor_sync(0xFFFFFFFFu, s0, 2);
            s1 += __shfl_xor_sync(0xFFFFFFFFu, s1, 1);
            s1 += __shfl_xor_sync(0xFFFFFFFFu, s1, 2);
            if ((lane & 3) == 0) {
                int d = mg * 32 + mt * 16 + (lane >> 2);
                partial[ng][d] = s0;
                partial[ng][d + 8] = s1;
            }
        }
        __syncthreads();   // partials visible; bt also free for next convert

        // ---- combine n-halves, coalesced store ----
        if (tid < D_DIM) out[(size_t)b * D_DIM + tid] = partial[0][tid] + partial[1][tid];

        cur = (cur + 1 >= 3) ? 0 : cur + 1;
    }
}

extern "C" void kernel_launch(void* const* d_in, const int* in_sizes, int n_in,
                              void* d_out, int out_size) {
    const float* inputs = (const float*)d_in[0];  // [16384, 50, 64] f32
    const float* theta = (const float*)d_in[1];   // [128, 50] f32
    float* out = (float*)d_out;                   // [16384, 128] f32
    (void)in_sizes; (void)n_in; (void)out_size;
    InnerProduct_65429531787441_kernel<<<GRID_CTAS, NTHREADS>>>(inputs, theta, out);
}

// round 14
// speedup vs baseline: 1.5148x; 1.5148x over previous
#include <cuda_runtime.h>
#include <cuda_fp16.h>
#include <cstdint>

#define B_TOT 16384
#define F_DIM 50
#define E_DIM 64
#define D_DIM 128
#define NTHREADS 128
#define CTAS_PER_SM 3
#define GRID_CTAS 444   // 148 SMs * 3 CTAs

// ---------------- helpers ----------------
__device__ __forceinline__ uint32_t smem_u32(const void* p) {
    uint32_t a;
    asm("{ .reg .u64 t; cvta.to.shared.u64 t, %1; cvt.u32.u64 %0, t; }" : "=r"(a) : "l"(p));
    return a;
}

__device__ __forceinline__ void cp_async16(uint32_t smem_addr, const void* gmem) {
    asm volatile("cp.async.cg.shared.global [%0], [%1], 16;" :: "r"(smem_addr), "l"(gmem));
}
__device__ __forceinline__ void cp_commit() { asm volatile("cp.async.commit_group;" ::: "memory"); }
__device__ __forceinline__ void cp_wait2() { asm volatile("cp.async.wait_group 2;" ::: "memory"); }

__device__ __forceinline__ void ldsm4t(uint32_t r[4], uint32_t addr) {
    asm volatile("ldmatrix.sync.aligned.m8n8.x4.trans.shared.b16 {%0,%1,%2,%3}, [%4];"
                 : "=r"(r[0]), "=r"(r[1]), "=r"(r[2]), "=r"(r[3]) : "r"(addr));
}

__device__ __forceinline__ void mma16816(float c[4], const uint32_t a[4], const uint32_t* b) {
    asm volatile(
        "mma.sync.aligned.m16n8k16.row.col.f32.f16.f16.f32 "
        "{%0,%1,%2,%3}, {%4,%5,%6,%7}, {%8,%9}, {%0,%1,%2,%3};"
        : "+f"(c[0]), "+f"(c[1]), "+f"(c[2]), "+f"(c[3])
        : "r"(a[0]), "r"(a[1]), "r"(a[2]), "r"(a[3]), "r"(b[0]), "r"(b[1]));
}

#define STS128(smem_addr, r0, r1, r2, r3) \
    asm volatile("st.shared.v4.b32 [%0], {%1, %2, %3, %4};" \
                 :: "r"(smem_addr), "r"(r0), "r"(r1), "r"(r2), "r"(r3) : "memory")

// Swizzled byte offset of element (k-row, n-col) in the 64x64 fp16 B tile.
// Rows are 128B; 16B atoms are XORed with (k&7) -> conflict-free STS + LDSM.
__device__ __forceinline__ uint32_t bt_off(int k, int n) {
    return (uint32_t)(k * 128 + ((((n >> 3) ^ k) & 7) << 4) + (n & 7) * 2);
}

// Pack theta[r][k0], theta[r][k0+1] as half2 (zero-padded beyond F_DIM).
__device__ __forceinline__ uint32_t ld_theta_h2(const float* theta, int r, int k0) {
    if (k0 < F_DIM) {   // k0 even, so k0 <= 48 implies k0+1 <= 49 valid
        float2 v = *reinterpret_cast<const float2*>(theta + r * F_DIM + k0);
        __half2 h = __floats2half2_rn(v.x, v.y);
        return *reinterpret_cast<uint32_t*>(&h);
    }
    return 0u;
}

// ---------------- kernel ----------------
__global__ void __launch_bounds__(NTHREADS, CTAS_PER_SM)
InnerProduct_65429531787441_kernel(const float* __restrict__ inputs,
                                   const float* __restrict__ theta,
                                   float* __restrict__ out) {
    __shared__ __align__(16) float stage[3][F_DIM * E_DIM];   // 3 x 12800 B ring
    __shared__ __align__(1024) __half bt[64 * 64];            // 8192 B swizzled B tile

    const int tid = threadIdx.x;
    const int lane = tid & 31;
    const int w = tid >> 5;
    const int mb = w * 32;                 // warp's M base (2 m-tiles of 16)
    const uint32_t bt_base = smem_u32(bt);
    uint32_t st_addr[3];
    st_addr[0] = smem_u32(&stage[0][0]);
    st_addr[1] = smem_u32(&stage[1][0]);
    st_addr[2] = smem_u32(&stage[2][0]);

    // Zero B rows 50..63 once (A frags are zero there, but avoid NaN garbage).
    if (tid < 112) reinterpret_cast<float4*>(bt)[400 + tid] = make_float4(0.f, 0.f, 0.f, 0.f);

    // ---- persistent A fragments: Theta, fp16, in registers ----
    uint32_t a[2][4][4];   // [m-tile][k-step][reg]
#pragma unroll
    for (int mt = 0; mt < 2; mt++)
#pragma unroll
        for (int ks = 0; ks < 4; ks++) {
            int r = mb + mt * 16 + (lane >> 2);
            int k0 = ks * 16 + (lane & 3) * 2;
            a[mt][ks][0] = ld_theta_h2(theta, r, k0);
            a[mt][ks][1] = ld_theta_h2(theta, r + 8, k0);
            a[mt][ks][2] = ld_theta_h2(theta, r, k0 + 8);
            a[mt][ks][3] = ld_theta_h2(theta, r + 8, k0 + 8);
        }
    __syncthreads();

    // ---- prologue: stage first two batches ----
    {
        const char* g0 = reinterpret_cast<const char*>(inputs + (size_t)blockIdx.x * (F_DIM * E_DIM));
#pragma unroll 2
        for (int i = tid; i < 800; i += NTHREADS) cp_async16(st_addr[0] + i * 16, g0 + i * 16);
        cp_commit();
        const int b1 = blockIdx.x + GRID_CTAS;
        if (b1 < B_TOT) {
            const char* g1 = reinterpret_cast<const char*>(inputs + (size_t)b1 * (F_DIM * E_DIM));
#pragma unroll 2
            for (int i = tid; i < 800; i += NTHREADS) cp_async16(st_addr[1] + i * 16, g1 + i * 16);
        }
        cp_commit();
    }

    int cur = 0;
    for (int b = blockIdx.x; b < B_TOT; b += GRID_CTAS) {
        // ---- prefetch b + 2*GRID into the stage consumed 2 iterations ago ----
        {
            const int bn = b + 2 * GRID_CTAS;
            if (bn < B_TOT) {
                const int pre = (cur + 2 >= 3) ? cur - 1 : cur + 2;
                const char* g = reinterpret_cast<const char*>(inputs + (size_t)bn * (F_DIM * E_DIM));
#pragma unroll 2
                for (int i = tid; i < 800; i += NTHREADS) cp_async16(st_addr[pre] + i * 16, g + i * 16);
            }
            cp_commit();            // constant one group per iteration (may be empty)
            cp_wait2();             // oldest group (batch b) complete
        }
        __syncthreads();

        // ---- convert f32 stage -> fp16 swizzled B tile (STS.128 granularity) ----
        {
            const float* sc = stage[cur];
#pragma unroll 4
            for (int i = tid; i < 400; i += NTHREADS) {   // 400 groups of 8 e-values
                int f = i >> 3;
                int e8 = (i & 7) * 8;
                const float4* p = reinterpret_cast<const float4*>(sc + f * 64 + e8);
                float4 v0 = p[0], v1 = p[1];
                __half2 h0 = __floats2half2_rn(v0.x, v0.y);
                __half2 h1 = __floats2half2_rn(v0.z, v0.w);
                __half2 h2 = __floats2half2_rn(v1.x, v1.y);
                __half2 h3 = __floats2half2_rn(v1.z, v1.w);
                uint32_t off = (uint32_t)(f * 128 + ((((e8 >> 3) ^ f) & 7) << 4));
                STS128(bt_base + off,
                       *reinterpret_cast<uint32_t*>(&h0), *reinterpret_cast<uint32_t*>(&h1),
                       *reinterpret_cast<uint32_t*>(&h2), *reinterpret_cast<uint32_t*>(&h3));
            }
        }
        __syncthreads();

        // ---- MMA: P(128x64) = Theta(128x64pad) * X(64x64), fp32 accum ----
        float c[2][8][4];
#pragma unroll
        for (int mt = 0; mt < 2; mt++)
#pragma unroll
            for (int nt = 0; nt < 8; nt++)
#pragma unroll
                for (int j = 0; j < 4; j++) c[mt][nt][j] = 0.f;

#pragma unroll
        for (int ks = 0; ks < 4; ks++) {
            uint32_t bf[8][2];
#pragma unroll
            for (int g = 0; g < 4; g++) {
                int t = lane >> 3;
                int k = ks * 16 + (t & 1) * 8 + (lane & 7);
                int n = g * 16 + (t >> 1) * 8;
                uint32_t r4[4];
                ldsm4t(r4, bt_base + bt_off(k, n));
                bf[2 * g][0] = r4[0]; bf[2 * g][1] = r4[1];
                bf[2 * g + 1][0] = r4[2]; bf[2 * g + 1][1] = r4[3];
            }
#pragma unroll
            for (int nt = 0; nt < 8; nt++) {
                mma16816(c[0][nt], a[0][ks], bf[nt]);
                mma16816(c[1][nt], a[1][ks], bf[nt]);
            }
        }

        // ---- epilogue: L_p[b,d] = sum_e P^2 (shuffle-only, no smem) ----
#pragma unroll
        for (int mt = 0; mt < 2; mt++) {
            float s0 = 0.f, s1 = 0.f;
#pragma unroll
            for (int nt = 0; nt < 8; nt++) {
                s0 = fmaf(c[mt][nt][0], c[mt][nt][0], s0);
                s0 = fmaf(c[mt][nt][1], c[mt][nt][1], s0);
                s1 = fmaf(c[mt][nt][2], c[mt][nt][2], s1);
                s1 = fmaf(c[mt][nt][3], c[mt][nt][3], s1);
            }
            s0 += __shfl_xor_sync(0xFFFFFFFFu, s0, 1);
            s0 += __shfl_xor_sync(0xFFFFFFFFu, s0, 2);
            s1 += __shfl_xor_sync(0xFFFFFFFFu, s1, 1);
            s1 += __shfl_xor_sync(0xFFFFFFFFu, s1, 2);
            if ((lane & 3) == 0) {
                int d = mb + mt * 16 + (lane >> 2);
                out[(size_t)b * D_DIM + d] = s0;
                out[(size_t)b * D_DIM + d + 8] = s1;
            }
        }
        __syncthreads();   // bt + stage[pre] rewritten next iteration
        cur = (cur + 1 >= 3) ? 0 : cur + 1;
    }
}

extern "C" void kernel_launch(void* const* d_in, const int* in_sizes, int n_in,
                              void* d_out, int out_size) {
    const float* inputs = (const float*)d_in[0];  // [16384, 50, 64] f32
    const float* theta = (const float*)d_in[1];   // [128, 50] f32
    float* out = (float*)d_out;                   // [16384, 128] f32
    (void)in_sizes; (void)n_in; (void)out_size;
    InnerProduct_65429531787441_kernel<<<GRID_CTAS, NTHREADS>>>(inputs, theta, out);
}